// round 6
// baseline (speedup 1.0000x reference)
#include <cuda_runtime.h>
#include <cuda_bf16.h>
#include <cstdint>

// ---------------------------------------------------------------------------
// Problem constants
// ---------------------------------------------------------------------------
#define NB      2
#define C_IN    16
#define NN      4096
#define TT      12
#define C_OUT   16
#define GDEP    2
#define ALPHA   0.05f

#define COLS    384
#define HSZ     (NN * COLS)

// GEMM tiling
#define BM      128
#define BN      192
#define BK      32
#define NT      (NN / BK)
#define PAD     36                      // floats per smem row
#define STAGE_F (BM * PAD + BN * PAD)   // 11520 floats
#define SM_BYTES (3 * STAGE_F * 4)      // 138240

// ---------------------------------------------------------------------------
// Device scratch
// ---------------------------------------------------------------------------
__device__ float g_Hs[GDEP + 1][HSZ];     // h0, h1, h2  [w][col]
__device__ float g_Y[4][HSZ];             // raw A@X per matrix [v][col]
__device__ float g_Xt[(size_t)COLS * NN]; // X^T, tf32-rounded [col][w]
__device__ float g_inv[3 * NN];           // 1/(rowsum+1) for a_i,a_j,a_k

// ---------------------------------------------------------------------------
// helpers
// ---------------------------------------------------------------------------
__device__ __forceinline__ float tf32r(float x) {
    uint32_t u;
    asm("cvt.rna.tf32.f32 %0, %1;" : "=r"(u) : "f"(x));
    return __uint_as_float(u);
}
__device__ __forceinline__ uint32_t smem_u32(const void* p) {
    uint32_t a;
    asm("{ .reg .u64 t; cvta.to.shared.u64 t, %1; cvt.u32.u64 %0, t; }"
        : "=r"(a) : "l"(p));
    return a;
}
__device__ __forceinline__ void cp_async16(uint32_t dst, const void* src) {
    asm volatile("cp.async.cg.shared.global [%0], [%1], 16;"
                 :: "r"(dst), "l"(src) : "memory");
}
__device__ __forceinline__ void cp_commit() {
    asm volatile("cp.async.commit_group;" ::: "memory");
}
__device__ __forceinline__ void cp_wait1() {
    asm volatile("cp.async.wait_group 1;" ::: "memory");
}
__device__ __forceinline__ void ldsm_x4(uint32_t* r, uint32_t addr) {
    asm volatile(
        "ldmatrix.sync.aligned.m8n8.x4.shared.b16 {%0,%1,%2,%3}, [%4];"
        : "=r"(r[0]), "=r"(r[1]), "=r"(r[2]), "=r"(r[3]) : "r"(addr));
}
__device__ __forceinline__ void mma_tf32(float* c, const uint32_t* a,
                                         const uint32_t* b) {
    asm volatile(
        "mma.sync.aligned.m16n8k8.row.col.f32.tf32.tf32.f32 "
        "{%0,%1,%2,%3}, {%4,%5,%6,%7}, {%8,%9}, {%0,%1,%2,%3};"
        : "+f"(c[0]), "+f"(c[1]), "+f"(c[2]), "+f"(c[3])
        : "r"(a[0]), "r"(a[1]), "r"(a[2]), "r"(a[3]), "r"(b[0]), "r"(b[1]));
}

// ---------------------------------------------------------------------------
// 1) row sums: g_inv = 1/(rowsum+1) for a_i, a_j, a_k
// ---------------------------------------------------------------------------
__global__ void __launch_bounds__(256)
rowsum_kernel(const float* __restrict__ Ai, const float* __restrict__ Aj,
              const float* __restrict__ Ak) {
    const int row = blockIdx.x;
    const int mat = blockIdx.y;
    const float* A = (mat == 0) ? Ai : (mat == 1) ? Aj : Ak;
    const float* base = A + (size_t)row * NN;

    float s = 0.0f;
    for (int w = threadIdx.x * 4; w < NN; w += 1024) {
        float4 v = *(const float4*)&base[w];
        s += v.x + v.y + v.z + v.w;
    }
    #pragma unroll
    for (int o = 16; o > 0; o >>= 1) s += __shfl_xor_sync(0xffffffffu, s, o);
    __shared__ float red[8];
    if ((threadIdx.x & 31) == 0) red[threadIdx.x >> 5] = s;
    __syncthreads();
    if (threadIdx.x == 0) {
        float tot = 0.0f;
        #pragma unroll
        for (int i = 0; i < 8; i++) tot += red[i];
        g_inv[mat * NN + row] = 1.0f / (tot + 1.0f);
    }
}

// ---------------------------------------------------------------------------
// 2) pack x -> g_Hs[0][w][col], col = q*96 + (b*4+c)*12 + t
// ---------------------------------------------------------------------------
__global__ void pack_kernel(const float* __restrict__ x) {
    int idx = blockIdx.x * blockDim.x + threadIdx.x;
    if (idx >= HSZ) return;
    int w   = idx / COLS;
    int col = idx - w * COLS;
    int q   = col / 96;
    int rem = col - q * 96;
    int bc  = rem / 12;
    int t   = rem - bc * 12;
    int b   = bc >> 2;
    int c   = bc & 3;
    g_Hs[0][idx] = x[(((size_t)b * C_IN + (q * 4 + c)) * NN + w) * TT + t];
}

// ---------------------------------------------------------------------------
// 3) transpose + tf32-round: g_Hs[s] [w][col] -> g_Xt [col][w]
// ---------------------------------------------------------------------------
__global__ void xpose_kernel(int s) {
    __shared__ float tile[32][33];
    const float* __restrict__ H = g_Hs[s];
    const int w0 = blockIdx.x * 32, c0 = blockIdx.y * 32;
    const int tx = threadIdx.x, ty = threadIdx.y;  // (32, 8)
    #pragma unroll
    for (int i = 0; i < 32; i += 8)
        tile[ty + i][tx] = H[(size_t)(w0 + ty + i) * COLS + c0 + tx];
    __syncthreads();
    #pragma unroll
    for (int i = 0; i < 32; i += 8)
        g_Xt[(size_t)(c0 + ty + i) * NN + w0 + tx] = tf32r(tile[tx][ty + i]);
}

// ---------------------------------------------------------------------------
// 4) tf32 mma.sync GEMM:  g_Y[m] = A_raw[m] @ g_Xt^T
//    A consumed directly from inputs (fp32 bits as tf32 = RZ truncation).
//    BM=128 BN=192 BK=32, 8 warps (2x4), warp 64x48, ldmatrix fragments.
// ---------------------------------------------------------------------------
__global__ void __launch_bounds__(256, 1)
qgemm_kernel(const float* __restrict__ Ar, const float* __restrict__ Ai,
             const float* __restrict__ Aj, const float* __restrict__ Ak) {
    extern __shared__ float sm[];
    const uint32_t sbase = smem_u32(sm);

    const int tid  = threadIdx.x;
    const int m    = blockIdx.z;
    const float* __restrict__ A = (m == 0) ? Ar : (m == 1) ? Ai
                                : (m == 2) ? Aj : Ak;
    const int vbase = blockIdx.x * BM;
    const int nbase = blockIdx.y * BN;

    const float* __restrict__ Ag0 = A + (size_t)vbase * NN;
    const float* __restrict__ Bg0 = g_Xt + (size_t)nbase * NN;

    const int wid  = tid >> 5, lane = tid & 31;
    const int wm   = (wid & 1) * 64;        // warp M offset
    const int wn   = (wid >> 1) * 48;       // warp N offset
    const int g    = lane >> 2, t = lane & 3;
    const int r8   = lane & 7, sub = lane >> 3;

    // per-lane ldmatrix byte offsets (within a stage)
    uint32_t aoff[4], boff[3];
    #pragma unroll
    for (int i = 0; i < 4; i++)
        aoff[i] = (uint32_t)(((wm + i * 16 + (sub & 1) * 8 + r8) * PAD
                              + (sub >> 1) * 4) * 4);
    #pragma unroll
    for (int p = 0; p < 3; p++)
        boff[p] = (uint32_t)(((BM + wn + p * 16 + (sub >> 1) * 8 + r8) * PAD
                              + (sub & 1) * 4) * 4);

    float acc[4][6][4];
    #pragma unroll
    for (int i = 0; i < 4; i++)
        #pragma unroll
        for (int j = 0; j < 6; j++)
            #pragma unroll
            for (int r = 0; r < 4; r++) acc[i][j][r] = 0.0f;

    auto load_stage = [&](int st, int kb) {
        const uint32_t ao = sbase + (uint32_t)(st * STAGE_F) * 4;
        const uint32_t bo = ao + (uint32_t)(BM * PAD) * 4;
        #pragma unroll
        for (int c = tid; c < 1024; c += 256) {
            const int row = c >> 3, seg = c & 7;
            cp_async16(ao + (uint32_t)(row * PAD + seg * 4) * 4,
                       Ag0 + (size_t)row * NN + kb + seg * 4);
        }
        #pragma unroll
        for (int c = tid; c < 1536; c += 256) {
            const int row = c >> 3, seg = c & 7;
            cp_async16(bo + (uint32_t)(row * PAD + seg * 4) * 4,
                       Bg0 + (size_t)row * NN + kb + seg * 4);
        }
    };

    load_stage(0, 0);  cp_commit();
    load_stage(1, BK); cp_commit();

    for (int kt = 0; kt < NT; kt++) {
        cp_wait1();
        __syncthreads();
        if (kt + 2 < NT) load_stage((kt + 2) % 3, (kt + 2) * BK);
        cp_commit();

        const uint32_t stage = sbase + (uint32_t)((kt % 3) * STAGE_F) * 4;

        #pragma unroll
        for (int kk = 0; kk < 4; kk++) {
            const uint32_t kb = stage + kk * 32;
            uint32_t af[4][4], bfr[12];
            ldsm_x4(af[0], kb + aoff[0]);
            ldsm_x4(af[1], kb + aoff[1]);
            ldsm_x4(af[2], kb + aoff[2]);
            ldsm_x4(af[3], kb + aoff[3]);
            ldsm_x4(&bfr[0], kb + boff[0]);
            ldsm_x4(&bfr[4], kb + boff[1]);
            ldsm_x4(&bfr[8], kb + boff[2]);
            #pragma unroll
            for (int i = 0; i < 4; i++)
                #pragma unroll
                for (int j = 0; j < 6; j++)
                    mma_tf32(acc[i][j], af[i], &bfr[j * 2]);
        }
    }

    // ---- epilogue: raw Y (normalization folded into combine) ----
    float* Ym = g_Y[m];
    #pragma unroll
    for (int i = 0; i < 4; i++) {
        const int r0 = vbase + wm + i * 16 + g;
        #pragma unroll
        for (int j = 0; j < 6; j++) {
            const int c0 = nbase + wn + j * 8 + 2 * t;
            *(float2*)&Ym[(size_t)r0 * COLS + c0] =
                make_float2(acc[i][j][0], acc[i][j][1]);
            *(float2*)&Ym[(size_t)(r0 + 8) * COLS + c0] =
                make_float2(acc[i][j][2], acc[i][j][3]);
        }
    }
}

// ---------------------------------------------------------------------------
// 5) Hamilton sign-combine + fold (+I, row-norm) + mixprop update
// ---------------------------------------------------------------------------
__global__ void combine_kernel(int s) {
    int idx = blockIdx.x * blockDim.x + threadIdx.x;
    if (idx >= HSZ) return;
    const int v   = idx / COLS;
    const int col = idx - v * COLS;
    const int p   = col / 96;
    const int c96 = col - p * 96;

    const int   qt[4][4] = {{0,1,2,3},{1,0,3,2},{2,3,0,1},{3,2,1,0}};
    const float st[4][4] = {{ 1.f,-1.f,-1.f,-1.f},
                            { 1.f, 1.f, 1.f,-1.f},
                            { 1.f,-1.f, 1.f, 1.f},
                            { 1.f, 1.f,-1.f, 1.f}};
    const float* __restrict__ H = g_Hs[s];
    float acc = 0.0f;
    #pragma unroll
    for (int mm = 0; mm < 4; mm++) {
        const size_t o = (size_t)v * COLS + qt[p][mm] * 96 + c96;
        float y = g_Y[mm][o];
        if (mm > 0) y = (y + H[o]) * g_inv[(mm - 1) * NN + v];
        acc += st[p][mm] * y;
    }
    g_Hs[s + 1][idx] = ALPHA * g_Hs[0][idx] + (1.0f - ALPHA) * acc;
}

// ---------------------------------------------------------------------------
// 6) final quaternion-weight projection
// ---------------------------------------------------------------------------
__global__ void project_kernel(const float* __restrict__ weight,
                               float* __restrict__ out) {
    __shared__ float ham[GDEP + 1][16][16];
    const int   widx[4][4] = {{0,1,2,3},{1,0,3,2},{2,3,0,1},{3,2,1,0}};
    const float sgn[4][4]  = {{ 1.f,-1.f,-1.f,-1.f},
                              { 1.f, 1.f,-1.f, 1.f},
                              { 1.f, 1.f, 1.f,-1.f},
                              { 1.f,-1.f, 1.f, 1.f}};
    for (int idx = threadIdx.x; idx < (GDEP + 1) * 256; idx += blockDim.x) {
        const int k  = idx >> 8;
        const int i  = (idx >> 4) & 15;
        const int j  = idx & 15;
        const int qi = i >> 2, a = i & 3;
        const int qj = j >> 2, bb = j & 3;
        ham[k][i][j] = sgn[qj][qi] * weight[(k * 4 + a) * 16 + widx[qj][qi] * 4 + bb];
    }
    __syncthreads();

    const int gidx = blockIdx.x * blockDim.x + threadIdx.x;
    if (gidx >= NB * NN * TT) return;
    const int t = gidx % TT;
    const int n = (gidx / TT) % NN;
    const int b = gidx / (TT * NN);

    float hv[(GDEP + 1) * 16];
    #pragma unroll
    for (int k = 0; k <= GDEP; k++)
        #pragma unroll
        for (int i = 0; i < 16; i++)
            hv[k * 16 + i] =
                g_Hs[k][(size_t)n * COLS + (i >> 2) * 96 + (b * 4 + (i & 3)) * 12 + t];

    #pragma unroll
    for (int j = 0; j < 16; j++) {
        float acc = 0.0f;
        #pragma unroll
        for (int k = 0; k <= GDEP; k++)
            #pragma unroll
            for (int i = 0; i < 16; i++)
                acc += hv[k * 16 + i] * ham[k][i][j];
        out[(((size_t)b * C_OUT + j) * NN + n) * TT + t] = acc;
    }
}

// ---------------------------------------------------------------------------
extern "C" void kernel_launch(void* const* d_in, const int* in_sizes, int n_in,
                              void* d_out, int out_size) {
    const float* x  = (const float*)d_in[0];
    const float* Ar = (const float*)d_in[1];
    const float* Ai = (const float*)d_in[2];
    const float* Aj = (const float*)d_in[3];
    const float* Ak = (const float*)d_in[4];
    const float* w  = (const float*)d_in[5];
    float* out = (float*)d_out;

    cudaFuncSetAttribute(qgemm_kernel,
                         cudaFuncAttributeMaxDynamicSharedMemorySize, SM_BYTES);

    rowsum_kernel<<<dim3(NN, 3), 256>>>(Ai, Aj, Ak);
    pack_kernel<<<(HSZ + 255) / 256, 256>>>(x);
    xpose_kernel<<<dim3(NN / 32, COLS / 32), dim3(32, 8)>>>(0);
    for (int s = 0; s < GDEP; s++) {
        qgemm_kernel<<<dim3(NN / BM, COLS / BN, 4), 256, SM_BYTES>>>(Ar, Ai, Aj, Ak);
        combine_kernel<<<(HSZ + 255) / 256, 256>>>(s);
        if (s == 0) xpose_kernel<<<dim3(NN / 32, COLS / 32), dim3(32, 8)>>>(1);
    }
    project_kernel<<<(NB * NN * TT + 255) / 256, 256>>>(w, out);
}

// round 7
// speedup vs baseline: 1.0511x; 1.0511x over previous
#include <cuda_runtime.h>
#include <cstdint>

// ---------------------------------------------------------------------------
// Problem constants
// ---------------------------------------------------------------------------
#define NB      2
#define C_IN    16
#define NN      4096
#define TT      12
#define C_OUT   16
#define GDEP    2
#define ALPHA   0.05f

#define COLS    384
#define HSZ     (NN * COLS)

// GEMM tiling (sized for 2 CTAs/SM)
#define BM      128
#define BN      96
#define BK      32
#define NT      (NN / BK)
#define PAD     36                      // floats per smem row
#define STAGE_F ((BM + BN) * PAD)       // 8064 floats
#define SM_BYTES (3 * STAGE_F * 4)      // 96768

// ---------------------------------------------------------------------------
// Device scratch
// ---------------------------------------------------------------------------
__device__ float g_Hs[GDEP + 1][HSZ];     // h0, h1, h2  [w][col]
__device__ float g_Y[4][HSZ];             // raw A@X per matrix [v][col]
__device__ float g_Xt[(size_t)COLS * NN]; // X^T, tf32-rounded [col][w]
__device__ float g_inv[3 * NN];           // 1/(rowsum+1) for a_i,a_j,a_k

// ---------------------------------------------------------------------------
// helpers
// ---------------------------------------------------------------------------
__device__ __forceinline__ float tf32r(float x) {
    uint32_t u;
    asm("cvt.rna.tf32.f32 %0, %1;" : "=r"(u) : "f"(x));
    return __uint_as_float(u);
}
__device__ __forceinline__ uint32_t smem_u32(const void* p) {
    uint32_t a;
    asm("{ .reg .u64 t; cvta.to.shared.u64 t, %1; cvt.u32.u64 %0, t; }"
        : "=r"(a) : "l"(p));
    return a;
}
__device__ __forceinline__ void cp_async16(uint32_t dst, const void* src) {
    asm volatile("cp.async.cg.shared.global [%0], [%1], 16;"
                 :: "r"(dst), "l"(src) : "memory");
}
__device__ __forceinline__ void cp_commit() {
    asm volatile("cp.async.commit_group;" ::: "memory");
}
__device__ __forceinline__ void cp_wait1() {
    asm volatile("cp.async.wait_group 1;" ::: "memory");
}
__device__ __forceinline__ void ldsm_x4(uint32_t* r, uint32_t addr) {
    asm volatile(
        "ldmatrix.sync.aligned.m8n8.x4.shared.b16 {%0,%1,%2,%3}, [%4];"
        : "=r"(r[0]), "=r"(r[1]), "=r"(r[2]), "=r"(r[3]) : "r"(addr));
}
__device__ __forceinline__ void mma_tf32(float* c, const uint32_t* a,
                                         const uint32_t* b) {
    asm volatile(
        "mma.sync.aligned.m16n8k8.row.col.f32.tf32.tf32.f32 "
        "{%0,%1,%2,%3}, {%4,%5,%6,%7}, {%8,%9}, {%0,%1,%2,%3};"
        : "+f"(c[0]), "+f"(c[1]), "+f"(c[2]), "+f"(c[3])
        : "r"(a[0]), "r"(a[1]), "r"(a[2]), "r"(a[3]), "r"(b[0]), "r"(b[1]));
}

// ---------------------------------------------------------------------------
// 1) row sums: g_inv = 1/(rowsum+1) for a_i, a_j, a_k
// ---------------------------------------------------------------------------
__global__ void __launch_bounds__(256)
rowsum_kernel(const float* __restrict__ Ai, const float* __restrict__ Aj,
              const float* __restrict__ Ak) {
    const int row = blockIdx.x;
    const int mat = blockIdx.y;
    const float* A = (mat == 0) ? Ai : (mat == 1) ? Aj : Ak;
    const float* base = A + (size_t)row * NN;

    float s = 0.0f;
    for (int w = threadIdx.x * 4; w < NN; w += 1024) {
        float4 v = *(const float4*)&base[w];
        s += v.x + v.y + v.z + v.w;
    }
    #pragma unroll
    for (int o = 16; o > 0; o >>= 1) s += __shfl_xor_sync(0xffffffffu, s, o);
    __shared__ float red[8];
    if ((threadIdx.x & 31) == 0) red[threadIdx.x >> 5] = s;
    __syncthreads();
    if (threadIdx.x == 0) {
        float tot = 0.0f;
        #pragma unroll
        for (int i = 0; i < 8; i++) tot += red[i];
        g_inv[mat * NN + row] = 1.0f / (tot + 1.0f);
    }
}

// ---------------------------------------------------------------------------
// 2) pack x -> g_Hs[0][w][col], col = q*96 + (b*4+c)*12 + t
// ---------------------------------------------------------------------------
__global__ void pack_kernel(const float* __restrict__ x) {
    int idx = blockIdx.x * blockDim.x + threadIdx.x;
    if (idx >= HSZ) return;
    int w   = idx / COLS;
    int col = idx - w * COLS;
    int q   = col / 96;
    int rem = col - q * 96;
    int bc  = rem / 12;
    int t   = rem - bc * 12;
    int b   = bc >> 2;
    int c   = bc & 3;
    g_Hs[0][idx] = x[(((size_t)b * C_IN + (q * 4 + c)) * NN + w) * TT + t];
}

// ---------------------------------------------------------------------------
// 3) transpose + tf32-round: g_Hs[s] [w][col] -> g_Xt [col][w]
// ---------------------------------------------------------------------------
__global__ void xpose_kernel(int s) {
    __shared__ float tile[32][33];
    const float* __restrict__ H = g_Hs[s];
    const int w0 = blockIdx.x * 32, c0 = blockIdx.y * 32;
    const int tx = threadIdx.x, ty = threadIdx.y;  // (32, 8)
    #pragma unroll
    for (int i = 0; i < 32; i += 8)
        tile[ty + i][tx] = H[(size_t)(w0 + ty + i) * COLS + c0 + tx];
    __syncthreads();
    #pragma unroll
    for (int i = 0; i < 32; i += 8)
        g_Xt[(size_t)(c0 + ty + i) * NN + w0 + tx] = tf32r(tile[tx][ty + i]);
}

// ---------------------------------------------------------------------------
// 4) tf32 mma.sync GEMM:  g_Y[m] = A_raw[m] @ g_Xt^T
//    BM=128 BN=96 BK=32, 4 warps (2x2), warp 64x48, 2 CTAs/SM.
// ---------------------------------------------------------------------------
__global__ void __launch_bounds__(128, 2)
qgemm_kernel(const float* __restrict__ Ar, const float* __restrict__ Ai,
             const float* __restrict__ Aj, const float* __restrict__ Ak) {
    extern __shared__ float sm[];
    const uint32_t sbase = smem_u32(sm);

    const int tid  = threadIdx.x;
    const int m    = blockIdx.z;
    const float* __restrict__ A = (m == 0) ? Ar : (m == 1) ? Ai
                                : (m == 2) ? Aj : Ak;
    const int vbase = blockIdx.x * BM;
    const int nbase = blockIdx.y * BN;

    const float* __restrict__ Ag0 = A + (size_t)vbase * NN;
    const float* __restrict__ Bg0 = g_Xt + (size_t)nbase * NN;

    const int wid  = tid >> 5, lane = tid & 31;
    const int wm   = (wid & 1) * 64;        // warp M offset
    const int wn   = (wid >> 1) * 48;       // warp N offset
    const int g    = lane >> 2, t = lane & 3;
    const int r8   = lane & 7, sub = lane >> 3;

    // per-lane ldmatrix byte offsets (within a stage)
    uint32_t aoff[4], boff[3];
    #pragma unroll
    for (int i = 0; i < 4; i++)
        aoff[i] = (uint32_t)(((wm + i * 16 + (sub & 1) * 8 + r8) * PAD
                              + (sub >> 1) * 4) * 4);
    #pragma unroll
    for (int p = 0; p < 3; p++)
        boff[p] = (uint32_t)(((BM + wn + p * 16 + (sub >> 1) * 8 + r8) * PAD
                              + (sub & 1) * 4) * 4);

    float acc[4][6][4];
    #pragma unroll
    for (int i = 0; i < 4; i++)
        #pragma unroll
        for (int j = 0; j < 6; j++)
            #pragma unroll
            for (int r = 0; r < 4; r++) acc[i][j][r] = 0.0f;

    auto load_stage = [&](int st, int kb) {
        const uint32_t ao = sbase + (uint32_t)(st * STAGE_F) * 4;
        const uint32_t bo = ao + (uint32_t)(BM * PAD) * 4;
        #pragma unroll
        for (int c = tid; c < 1024; c += 128) {   // A: 128 rows x 8 chunks
            const int row = c >> 3, seg = c & 7;
            cp_async16(ao + (uint32_t)(row * PAD + seg * 4) * 4,
                       Ag0 + (size_t)row * NN + kb + seg * 4);
        }
        #pragma unroll
        for (int c = tid; c < 768; c += 128) {    // B: 96 rows x 8 chunks
            const int row = c >> 3, seg = c & 7;
            cp_async16(bo + (uint32_t)(row * PAD + seg * 4) * 4,
                       Bg0 + (size_t)row * NN + kb + seg * 4);
        }
    };

    load_stage(0, 0);  cp_commit();
    load_stage(1, BK); cp_commit();

    for (int kt = 0; kt < NT; kt++) {
        cp_wait1();
        __syncthreads();
        if (kt + 2 < NT) load_stage((kt + 2) % 3, (kt + 2) * BK);
        cp_commit();

        const uint32_t stage = sbase + (uint32_t)((kt % 3) * STAGE_F) * 4;

        #pragma unroll
        for (int kk = 0; kk < 4; kk++) {
            const uint32_t kb = stage + kk * 32;
            uint32_t af[4][4], bfr[12];
            ldsm_x4(af[0], kb + aoff[0]);
            ldsm_x4(af[1], kb + aoff[1]);
            ldsm_x4(af[2], kb + aoff[2]);
            ldsm_x4(af[3], kb + aoff[3]);
            ldsm_x4(&bfr[0], kb + boff[0]);
            ldsm_x4(&bfr[4], kb + boff[1]);
            ldsm_x4(&bfr[8], kb + boff[2]);
            #pragma unroll
            for (int i = 0; i < 4; i++)
                #pragma unroll
                for (int j = 0; j < 6; j++)
                    mma_tf32(acc[i][j], af[i], &bfr[j * 2]);
        }
    }

    // ---- epilogue: raw Y (normalization folded into combine) ----
    float* Ym = g_Y[m];
    #pragma unroll
    for (int i = 0; i < 4; i++) {
        const int r0 = vbase + wm + i * 16 + g;
        #pragma unroll
        for (int j = 0; j < 6; j++) {
            const int c0 = nbase + wn + j * 8 + 2 * t;
            *(float2*)&Ym[(size_t)r0 * COLS + c0] =
                make_float2(acc[i][j][0], acc[i][j][1]);
            *(float2*)&Ym[(size_t)(r0 + 8) * COLS + c0] =
                make_float2(acc[i][j][2], acc[i][j][3]);
        }
    }
}

// ---------------------------------------------------------------------------
// 5) Hamilton sign-combine + fold (+I, row-norm) + mixprop update
// ---------------------------------------------------------------------------
__global__ void combine_kernel(int s) {
    int idx = blockIdx.x * blockDim.x + threadIdx.x;
    if (idx >= HSZ) return;
    const int v   = idx / COLS;
    const int col = idx - v * COLS;
    const int p   = col / 96;
    const int c96 = col - p * 96;

    const int   qt[4][4] = {{0,1,2,3},{1,0,3,2},{2,3,0,1},{3,2,1,0}};
    const float st[4][4] = {{ 1.f,-1.f,-1.f,-1.f},
                            { 1.f, 1.f, 1.f,-1.f},
                            { 1.f,-1.f, 1.f, 1.f},
                            { 1.f, 1.f,-1.f, 1.f}};
    const float* __restrict__ H = g_Hs[s];
    float acc = 0.0f;
    #pragma unroll
    for (int mm = 0; mm < 4; mm++) {
        const size_t o = (size_t)v * COLS + qt[p][mm] * 96 + c96;
        float y = g_Y[mm][o];
        if (mm > 0) y = (y + H[o]) * g_inv[(mm - 1) * NN + v];
        acc += st[p][mm] * y;
    }
    g_Hs[s + 1][idx] = ALPHA * g_Hs[0][idx] + (1.0f - ALPHA) * acc;
}

// ---------------------------------------------------------------------------
// 6) final quaternion-weight projection
// ---------------------------------------------------------------------------
__global__ void project_kernel(const float* __restrict__ weight,
                               float* __restrict__ out) {
    __shared__ float ham[GDEP + 1][16][16];
    const int   widx[4][4] = {{0,1,2,3},{1,0,3,2},{2,3,0,1},{3,2,1,0}};
    const float sgn[4][4]  = {{ 1.f,-1.f,-1.f,-1.f},
                              { 1.f, 1.f,-1.f, 1.f},
                              { 1.f, 1.f, 1.f,-1.f},
                              { 1.f,-1.f, 1.f, 1.f}};
    for (int idx = threadIdx.x; idx < (GDEP + 1) * 256; idx += blockDim.x) {
        const int k  = idx >> 8;
        const int i  = (idx >> 4) & 15;
        const int j  = idx & 15;
        const int qi = i >> 2, a = i & 3;
        const int qj = j >> 2, bb = j & 3;
        ham[k][i][j] = sgn[qj][qi] * weight[(k * 4 + a) * 16 + widx[qj][qi] * 4 + bb];
    }
    __syncthreads();

    const int gidx = blockIdx.x * blockDim.x + threadIdx.x;
    if (gidx >= NB * NN * TT) return;
    const int t = gidx % TT;
    const int n = (gidx / TT) % NN;
    const int b = gidx / (TT * NN);

    float hv[(GDEP + 1) * 16];
    #pragma unroll
    for (int k = 0; k <= GDEP; k++)
        #pragma unroll
        for (int i = 0; i < 16; i++)
            hv[k * 16 + i] =
                g_Hs[k][(size_t)n * COLS + (i >> 2) * 96 + (b * 4 + (i & 3)) * 12 + t];

    #pragma unroll
    for (int j = 0; j < 16; j++) {
        float acc = 0.0f;
        #pragma unroll
        for (int k = 0; k <= GDEP; k++)
            #pragma unroll
            for (int i = 0; i < 16; i++)
                acc += hv[k * 16 + i] * ham[k][i][j];
        out[(((size_t)b * C_OUT + j) * NN + n) * TT + t] = acc;
    }
}

// ---------------------------------------------------------------------------
extern "C" void kernel_launch(void* const* d_in, const int* in_sizes, int n_in,
                              void* d_out, int out_size) {
    const float* x  = (const float*)d_in[0];
    const float* Ar = (const float*)d_in[1];
    const float* Ai = (const float*)d_in[2];
    const float* Aj = (const float*)d_in[3];
    const float* Ak = (const float*)d_in[4];
    const float* w  = (const float*)d_in[5];
    float* out = (float*)d_out;

    cudaFuncSetAttribute(qgemm_kernel,
                         cudaFuncAttributeMaxDynamicSharedMemorySize, SM_BYTES);

    rowsum_kernel<<<dim3(NN, 3), 256>>>(Ai, Aj, Ak);
    pack_kernel<<<(HSZ + 255) / 256, 256>>>(x);
    xpose_kernel<<<dim3(NN / 32, COLS / 32), dim3(32, 8)>>>(0);
    for (int s = 0; s < GDEP; s++) {
        qgemm_kernel<<<dim3(NN / BM, COLS / BN, 4), 128, SM_BYTES>>>(Ar, Ai, Aj, Ak);
        combine_kernel<<<(HSZ + 255) / 256, 256>>>(s);
        if (s == 0) xpose_kernel<<<dim3(NN / 32, COLS / 32), dim3(32, 8)>>>(1);
    }
    project_kernel<<<(NB * NN * TT + 255) / 256, 256>>>(w, out);
}

// round 8
// speedup vs baseline: 1.9259x; 1.8322x over previous
#include <cuda_runtime.h>
#include <cuda_fp16.h>
#include <cstdint>

// ---------------------------------------------------------------------------
// Problem constants
// ---------------------------------------------------------------------------
#define NB      2
#define C_IN    16
#define NN      4096
#define TT      12
#define C_OUT   16
#define GDEP    2
#define ALPHA   0.05f

#define COLS    384
#define HSZ     (NN * COLS)
#define MSZ     ((size_t)NN * NN)

// GEMM tiling (fp16 operands, 2 CTAs/SM)
#define BM      128
#define BN      96
#define BK      32
#define NT      (NN / BK)
#define PADH    40                      // halves per smem row (80 B pitch)
#define STAGE_H ((BM + BN) * PADH)      // 8960 halves = 17920 B
#define SM_BYTES (3 * STAGE_H * 2)      // 53760

// ---------------------------------------------------------------------------
// Device scratch
// ---------------------------------------------------------------------------
__device__ float  g_Hs[GDEP + 1][HSZ];    // h0, h1, h2  [w][col]
__device__ float  g_Y[4][HSZ];            // A_eff@X per matrix [v][col]
__device__ __half g_Ah[4 * MSZ];          // A_eff fp16 [m][row][k] (fold +I,norm)
__device__ __half g_Xh[(size_t)COLS * NN];// X^T fp16 [col][w]

// ---------------------------------------------------------------------------
// helpers
// ---------------------------------------------------------------------------
__device__ __forceinline__ uint32_t smem_u32(const void* p) {
    uint32_t a;
    asm("{ .reg .u64 t; cvta.to.shared.u64 t, %1; cvt.u32.u64 %0, t; }"
        : "=r"(a) : "l"(p));
    return a;
}
__device__ __forceinline__ void cp_async16(uint32_t dst, const void* src) {
    asm volatile("cp.async.cg.shared.global [%0], [%1], 16;"
                 :: "r"(dst), "l"(src) : "memory");
}
__device__ __forceinline__ void cp_commit() {
    asm volatile("cp.async.commit_group;" ::: "memory");
}
__device__ __forceinline__ void cp_wait1() {
    asm volatile("cp.async.wait_group 1;" ::: "memory");
}
__device__ __forceinline__ void ldsm_x4(uint32_t* r, uint32_t addr) {
    asm volatile(
        "ldmatrix.sync.aligned.m8n8.x4.shared.b16 {%0,%1,%2,%3}, [%4];"
        : "=r"(r[0]), "=r"(r[1]), "=r"(r[2]), "=r"(r[3]) : "r"(addr));
}
__device__ __forceinline__ void mma_f16(float* c, const uint32_t* a,
                                        const uint32_t* b) {
    asm volatile(
        "mma.sync.aligned.m16n8k16.row.col.f32.f16.f16.f32 "
        "{%0,%1,%2,%3}, {%4,%5,%6,%7}, {%8,%9}, {%0,%1,%2,%3};"
        : "+f"(c[0]), "+f"(c[1]), "+f"(c[2]), "+f"(c[3])
        : "r"(a[0]), "r"(a[1]), "r"(a[2]), "r"(a[3]), "r"(b[0]), "r"(b[1]));
}

// ---------------------------------------------------------------------------
// 1) A_eff prepass: fold (+I, row-norm) for m>0, convert to fp16 (rn)
// ---------------------------------------------------------------------------
__global__ void __launch_bounds__(256)
a2h_kernel(const float* __restrict__ Ar, const float* __restrict__ Ai,
           const float* __restrict__ Aj, const float* __restrict__ Ak) {
    const int row = blockIdx.x;
    const int m = blockIdx.y;
    const float* A = (m == 0) ? Ar : (m == 1) ? Ai : (m == 2) ? Aj : Ak;
    const float* rp = A + (size_t)row * NN;

    __shared__ float red[8];
    float inv = 1.0f;
    if (m > 0) {
        float s = 0.0f;
        for (int k = threadIdx.x * 4; k < NN; k += 1024) {
            float4 v = *(const float4*)&rp[k];
            s += v.x + v.y + v.z + v.w;
        }
        #pragma unroll
        for (int o = 16; o > 0; o >>= 1) s += __shfl_xor_sync(0xffffffffu, s, o);
        if ((threadIdx.x & 31) == 0) red[threadIdx.x >> 5] = s;
        __syncthreads();
        float tot = 0.0f;
        #pragma unroll
        for (int i = 0; i < 8; i++) tot += red[i];
        inv = 1.0f / (tot + 1.0f);
    }

    __half* op = g_Ah + (size_t)m * MSZ + (size_t)row * NN;
    for (int k = threadIdx.x * 4; k < NN; k += 1024) {
        float4 v = *(const float4*)&rp[k];
        float vals[4] = {v.x, v.y, v.z, v.w};
        __half h4[4];
        #pragma unroll
        for (int u = 0; u < 4; u++) {
            float val = vals[u];
            if (m > 0) val = (val + ((k + u) == row ? 1.0f : 0.0f)) * inv;
            h4[u] = __float2half_rn(val);
        }
        *(uint2*)&op[k] = *(uint2*)h4;
    }
}

// ---------------------------------------------------------------------------
// 2) pack x -> g_Hs[0][w][col], col = q*96 + (b*4+c)*12 + t
// ---------------------------------------------------------------------------
__global__ void pack_kernel(const float* __restrict__ x) {
    int idx = blockIdx.x * blockDim.x + threadIdx.x;
    if (idx >= HSZ) return;
    int w   = idx / COLS;
    int col = idx - w * COLS;
    int q   = col / 96;
    int rem = col - q * 96;
    int bc  = rem / 12;
    int t   = rem - bc * 12;
    int b   = bc >> 2;
    int c   = bc & 3;
    g_Hs[0][idx] = x[(((size_t)b * C_IN + (q * 4 + c)) * NN + w) * TT + t];
}

// ---------------------------------------------------------------------------
// 3) transpose + fp16 convert: g_Hs[s] [w][col] -> g_Xh [col][w]
// ---------------------------------------------------------------------------
__global__ void xpose_kernel(int s) {
    __shared__ float tile[32][33];
    const float* __restrict__ H = g_Hs[s];
    const int w0 = blockIdx.x * 32, c0 = blockIdx.y * 32;
    const int tx = threadIdx.x, ty = threadIdx.y;  // (32, 8)
    #pragma unroll
    for (int i = 0; i < 32; i += 8)
        tile[ty + i][tx] = H[(size_t)(w0 + ty + i) * COLS + c0 + tx];
    __syncthreads();
    #pragma unroll
    for (int i = 0; i < 32; i += 8)
        g_Xh[(size_t)(c0 + ty + i) * NN + w0 + tx] =
            __float2half_rn(tile[tx][ty + i]);
}

// ---------------------------------------------------------------------------
// 4) fp16 mma.sync GEMM:  g_Y[m] = g_Ah[m] @ g_Xh^T  (fp32 accum)
//    BM=128 BN=96 BK=32, 4 warps (2x2), warp 64x48, 2 CTAs/SM.
//    m16n8k16: 2x MACs per HMMA vs tf32 m16n8k8.
// ---------------------------------------------------------------------------
__global__ void __launch_bounds__(128, 2)
qgemm_kernel() {
    extern __shared__ __half sm[];
    const uint32_t sbase = smem_u32(sm);

    const int tid  = threadIdx.x;
    const int m    = blockIdx.z;
    const int vbase = blockIdx.x * BM;
    const int nbase = blockIdx.y * BN;

    const __half* __restrict__ Ag0 = g_Ah + (size_t)m * MSZ + (size_t)vbase * NN;
    const __half* __restrict__ Bg0 = g_Xh + (size_t)nbase * NN;

    const int wid  = tid >> 5, lane = tid & 31;
    const int wm   = (wid & 1) * 64;        // warp M offset
    const int wn   = (wid >> 1) * 48;       // warp N offset
    const int g    = lane >> 2, t = lane & 3;
    const int r8   = lane & 7, sub = lane >> 3;

    // per-lane ldmatrix byte offsets (within a stage)
    // A (m16k16 frags): rows wm+i*16+(sub&1)*8+r8, k-half = (sub>>1)*8 halves
    uint32_t aoff[4], boff[3];
    #pragma unroll
    for (int i = 0; i < 4; i++)
        aoff[i] = (uint32_t)((wm + i * 16 + (sub & 1) * 8 + r8) * PADH * 2
                             + (sub >> 1) * 16);
    // B (n16k16 frags, 2 j-tiles per ldsm): rows BM+wn+p*16+(sub>>1)*8+r8,
    // k-half = (sub&1)*8 halves
    #pragma unroll
    for (int p = 0; p < 3; p++)
        boff[p] = (uint32_t)((BM + wn + p * 16 + (sub >> 1) * 8 + r8) * PADH * 2
                             + (sub & 1) * 16);

    float acc[4][6][4];
    #pragma unroll
    for (int i = 0; i < 4; i++)
        #pragma unroll
        for (int j = 0; j < 6; j++)
            #pragma unroll
            for (int r = 0; r < 4; r++) acc[i][j][r] = 0.0f;

    auto load_stage = [&](int st, int kb) {
        const uint32_t ao = sbase + (uint32_t)(st * STAGE_H) * 2;
        const uint32_t bo = ao + (uint32_t)(BM * PADH) * 2;
        #pragma unroll
        for (int c = tid; c < 512; c += 128) {   // A: 128 rows x 4 x 16B
            const int row = c >> 2, seg = c & 3;
            cp_async16(ao + (uint32_t)(row * PADH * 2 + seg * 16),
                       Ag0 + (size_t)row * NN + kb + seg * 8);
        }
        #pragma unroll
        for (int c = tid; c < 384; c += 128) {   // B: 96 rows x 4 x 16B
            const int row = c >> 2, seg = c & 3;
            cp_async16(bo + (uint32_t)(row * PADH * 2 + seg * 16),
                       Bg0 + (size_t)row * NN + kb + seg * 8);
        }
    };

    load_stage(0, 0);  cp_commit();
    load_stage(1, BK); cp_commit();

    for (int kt = 0; kt < NT; kt++) {
        cp_wait1();
        __syncthreads();
        if (kt + 2 < NT) load_stage((kt + 2) % 3, (kt + 2) * BK);
        cp_commit();

        const uint32_t stage = sbase + (uint32_t)((kt % 3) * STAGE_H) * 2;

        #pragma unroll
        for (int kk = 0; kk < 2; kk++) {         // 2 x k16 per BK=32
            const uint32_t kb = stage + kk * 32; // 16 halves = 32 B
            uint32_t af[4][4], bfr[12];
            ldsm_x4(af[0], kb + aoff[0]);
            ldsm_x4(af[1], kb + aoff[1]);
            ldsm_x4(af[2], kb + aoff[2]);
            ldsm_x4(af[3], kb + aoff[3]);
            ldsm_x4(&bfr[0], kb + boff[0]);      // j0 (b0,b1), j1 (b0,b1)
            ldsm_x4(&bfr[4], kb + boff[1]);      // j2, j3
            ldsm_x4(&bfr[8], kb + boff[2]);      // j4, j5
            #pragma unroll
            for (int i = 0; i < 4; i++)
                #pragma unroll
                for (int j = 0; j < 6; j++)
                    mma_f16(acc[i][j], af[i], &bfr[j * 2]);
        }
    }

    // ---- epilogue ----
    float* Ym = g_Y[m];
    #pragma unroll
    for (int i = 0; i < 4; i++) {
        const int r0 = vbase + wm + i * 16 + g;
        #pragma unroll
        for (int j = 0; j < 6; j++) {
            const int c0 = nbase + wn + j * 8 + 2 * t;
            *(float2*)&Ym[(size_t)r0 * COLS + c0] =
                make_float2(acc[i][j][0], acc[i][j][1]);
            *(float2*)&Ym[(size_t)(r0 + 8) * COLS + c0] =
                make_float2(acc[i][j][2], acc[i][j][3]);
        }
    }
}

// ---------------------------------------------------------------------------
// 5) Hamilton sign-combine + mixprop update (normalization folded into A)
// ---------------------------------------------------------------------------
__global__ void combine_kernel(int s) {
    int idx = blockIdx.x * blockDim.x + threadIdx.x;
    if (idx >= HSZ) return;
    const int v   = idx / COLS;
    const int col = idx - v * COLS;
    const int p   = col / 96;
    const int c96 = col - p * 96;

    const int   qt[4][4] = {{0,1,2,3},{1,0,3,2},{2,3,0,1},{3,2,1,0}};
    const float st[4][4] = {{ 1.f,-1.f,-1.f,-1.f},
                            { 1.f, 1.f, 1.f,-1.f},
                            { 1.f,-1.f, 1.f, 1.f},
                            { 1.f, 1.f,-1.f, 1.f}};
    float acc = 0.0f;
    #pragma unroll
    for (int mm = 0; mm < 4; mm++)
        acc += st[p][mm] * g_Y[mm][(size_t)v * COLS + qt[p][mm] * 96 + c96];

    g_Hs[s + 1][idx] = ALPHA * g_Hs[0][idx] + (1.0f - ALPHA) * acc;
}

// ---------------------------------------------------------------------------
// 6) final quaternion-weight projection
// ---------------------------------------------------------------------------
__global__ void project_kernel(const float* __restrict__ weight,
                               float* __restrict__ out) {
    __shared__ float ham[GDEP + 1][16][16];
    const int   widx[4][4] = {{0,1,2,3},{1,0,3,2},{2,3,0,1},{3,2,1,0}};
    const float sgn[4][4]  = {{ 1.f,-1.f,-1.f,-1.f},
                              { 1.f, 1.f,-1.f, 1.f},
                              { 1.f, 1.f, 1.f,-1.f},
                              { 1.f,-1.f, 1.f, 1.f}};
    for (int idx = threadIdx.x; idx < (GDEP + 1) * 256; idx += blockDim.x) {
        const int k  = idx >> 8;
        const int i  = (idx >> 4) & 15;
        const int j  = idx & 15;
        const int qi = i >> 2, a = i & 3;
        const int qj = j >> 2, bb = j & 3;
        ham[k][i][j] = sgn[qj][qi] * weight[(k * 4 + a) * 16 + widx[qj][qi] * 4 + bb];
    }
    __syncthreads();

    const int gidx = blockIdx.x * blockDim.x + threadIdx.x;
    if (gidx >= NB * NN * TT) return;
    const int t = gidx % TT;
    const int n = (gidx / TT) % NN;
    const int b = gidx / (TT * NN);

    float hv[(GDEP + 1) * 16];
    #pragma unroll
    for (int k = 0; k <= GDEP; k++)
        #pragma unroll
        for (int i = 0; i < 16; i++)
            hv[k * 16 + i] =
                g_Hs[k][(size_t)n * COLS + (i >> 2) * 96 + (b * 4 + (i & 3)) * 12 + t];

    #pragma unroll
    for (int j = 0; j < 16; j++) {
        float acc = 0.0f;
        #pragma unroll
        for (int k = 0; k <= GDEP; k++)
            #pragma unroll
            for (int i = 0; i < 16; i++)
                acc += hv[k * 16 + i] * ham[k][i][j];
        out[(((size_t)b * C_OUT + j) * NN + n) * TT + t] = acc;
    }
}

// ---------------------------------------------------------------------------
extern "C" void kernel_launch(void* const* d_in, const int* in_sizes, int n_in,
                              void* d_out, int out_size) {
    const float* x  = (const float*)d_in[0];
    const float* Ar = (const float*)d_in[1];
    const float* Ai = (const float*)d_in[2];
    const float* Aj = (const float*)d_in[3];
    const float* Ak = (const float*)d_in[4];
    const float* w  = (const float*)d_in[5];
    float* out = (float*)d_out;

    cudaFuncSetAttribute(qgemm_kernel,
                         cudaFuncAttributeMaxDynamicSharedMemorySize, SM_BYTES);

    a2h_kernel<<<dim3(NN, 4), 256>>>(Ar, Ai, Aj, Ak);
    pack_kernel<<<(HSZ + 255) / 256, 256>>>(x);
    xpose_kernel<<<dim3(NN / 32, COLS / 32), dim3(32, 8)>>>(0);
    for (int s = 0; s < GDEP; s++) {
        qgemm_kernel<<<dim3(NN / BM, COLS / BN, 4), 128, SM_BYTES>>>();
        combine_kernel<<<(HSZ + 255) / 256, 256>>>(s);
        if (s == 0) xpose_kernel<<<dim3(NN / 32, COLS / 32), dim3(32, 8)>>>(1);
    }
    project_kernel<<<(NB * NN * TT + 255) / 256, 256>>>(w, out);
}